// round 1
// baseline (speedup 1.0000x reference)
#include <cuda_runtime.h>
#include <cstdint>

#define NUM_USERS 100000
#define NUM_ITEMS 200000
#define N_TOTAL   300000
#define EMBED_DIM 64
#define NNZ       4000000
#define BATCH     16384

// Node-feature matrices as float4 rows: 16 float4 per node (64 floats).
// Scratch lives in __device__ globals (no cudaMalloc allowed).
__device__ float4 g_x0[(size_t)N_TOTAL * 16];
__device__ float4 g_x1[(size_t)N_TOTAL * 16];
__device__ float4 g_acc[(size_t)N_TOTAL * 16];

// ---------------------------------------------------------------------------
// init: x0 = concat(user_emb, item_emb); acc = x0; x1 = 0
// ---------------------------------------------------------------------------
__global__ void init_kernel(const float4* __restrict__ uw,
                            const float4* __restrict__ iw) {
    int idx = blockIdx.x * blockDim.x + threadIdx.x;
    const int total = N_TOTAL * 16;
    if (idx >= total) return;
    int row = idx >> 4;
    float4 v = (row < NUM_USERS) ? uw[idx] : iw[idx - NUM_USERS * 16];
    g_x0[idx]  = v;
    g_acc[idx] = v;
    g_x1[idx]  = make_float4(0.f, 0.f, 0.f, 0.f);
}

// ---------------------------------------------------------------------------
// spmm: dst[row] += val * src[col] for every COO edge.
// 16 threads per edge, one float4 each -> 256B coalesced gather + 4x red.v4.
// srcsel==0: x0 -> x1 ; srcsel==1: x1 -> x0
// ---------------------------------------------------------------------------
__global__ void spmm_kernel(const int*   __restrict__ rows,
                            const int*   __restrict__ cols,
                            const float* __restrict__ vals,
                            int srcsel) {
    const float4* src = (srcsel == 0) ? g_x0 : g_x1;
    float*        dst = (srcsel == 0) ? (float*)g_x1 : (float*)g_x0;

    unsigned int tid = blockIdx.x * blockDim.x + threadIdx.x;
    if (tid >= (unsigned int)NNZ * 16u) return;
    int e = (int)(tid >> 4);
    int c = (int)(tid & 15u);

    int   r  = __ldg(rows + e);
    int   cl = __ldg(cols + e);
    float v  = __ldg(vals + e);

    float4 x = __ldg(src + ((size_t)cl * 16 + c));

    float* p = dst + ((size_t)r * 64 + (size_t)c * 4);
    unsigned long long gp = __cvta_generic_to_global(p);
    asm volatile("red.global.add.v4.f32 [%0], {%1, %2, %3, %4};"
                 :: "l"(gp), "f"(x.x * v), "f"(x.y * v),
                    "f"(x.z * v), "f"(x.w * v)
                 : "memory");
}

// ---------------------------------------------------------------------------
// combine: acc += src; optionally zero the buffer the NEXT spmm writes into.
// srcsel selects which buffer was just written (0 -> x0, 1 -> x1).
// ---------------------------------------------------------------------------
__global__ void combine_kernel(int srcsel, int do_clear) {
    int idx = blockIdx.x * blockDim.x + threadIdx.x;
    const int total = N_TOTAL * 16;
    if (idx >= total) return;

    const float4* src   = (srcsel == 0) ? g_x0 : g_x1;
    float4*       clear = (srcsel == 0) ? g_x1 : g_x0;

    float4 a = g_acc[idx];
    float4 s = src[idx];
    a.x += s.x; a.y += s.y; a.z += s.z; a.w += s.w;
    g_acc[idx] = a;
    if (do_clear) clear[idx] = make_float4(0.f, 0.f, 0.f, 0.f);
}

// ---------------------------------------------------------------------------
// final: out[b] = dot(acc[u], acc[i + NUM_USERS]) / 16
// (each side of the dot carries an implicit /(NUM_LAYERS+1)=/4)
// 16 threads per batch element, shfl-reduce within the group.
// ---------------------------------------------------------------------------
__global__ void final_kernel(const int* __restrict__ uid,
                             const int* __restrict__ iid,
                             float* __restrict__ out) {
    int tid = blockIdx.x * blockDim.x + threadIdx.x;
    if (tid >= BATCH * 16) return;
    int b = tid >> 4;
    int c = tid & 15;

    int u  = __ldg(uid + b);
    int it = __ldg(iid + b) + NUM_USERS;

    float4 a  = g_acc[(size_t)u  * 16 + c];
    float4 bb = g_acc[(size_t)it * 16 + c];
    float s = a.x * bb.x + a.y * bb.y + a.z * bb.z + a.w * bb.w;

    #pragma unroll
    for (int o = 8; o > 0; o >>= 1)
        s += __shfl_down_sync(0xffffffffu, s, o, 16);

    if (c == 0) out[b] = s * (1.0f / 16.0f);
}

// ---------------------------------------------------------------------------
// kernel_launch
// inputs (metadata order): user_ids, item_ids, adj_row, adj_col, adj_val,
//                          user_emb_w, item_emb_w
// output: float[BATCH]
// ---------------------------------------------------------------------------
extern "C" void kernel_launch(void* const* d_in, const int* in_sizes, int n_in,
                              void* d_out, int out_size) {
    const int*   uid  = (const int*)  d_in[0];
    const int*   iid  = (const int*)  d_in[1];
    const int*   rows = (const int*)  d_in[2];
    const int*   cols = (const int*)  d_in[3];
    const float* vals = (const float*)d_in[4];
    const float4* uw  = (const float4*)d_in[5];
    const float4* iw  = (const float4*)d_in[6];
    float* out = (float*)d_out;

    const int TB = 256;
    const int init_blocks  = (N_TOTAL * 16 + TB - 1) / TB;
    const unsigned int spmm_threads = (unsigned int)NNZ * 16u;
    const int spmm_blocks  = (int)((spmm_threads + TB - 1) / TB);
    const int final_blocks = (BATCH * 16 + TB - 1) / TB;

    init_kernel<<<init_blocks, TB>>>(uw, iw);

    // layer 1: x0 -> x1, acc += x1, zero x0
    spmm_kernel<<<spmm_blocks, TB>>>(rows, cols, vals, 0);
    combine_kernel<<<init_blocks, TB>>>(1, 1);

    // layer 2: x1 -> x0, acc += x0, zero x1
    spmm_kernel<<<spmm_blocks, TB>>>(rows, cols, vals, 1);
    combine_kernel<<<init_blocks, TB>>>(0, 1);

    // layer 3: x0 -> x1, acc += x1 (no clear needed)
    spmm_kernel<<<spmm_blocks, TB>>>(rows, cols, vals, 0);
    combine_kernel<<<init_blocks, TB>>>(1, 0);

    final_kernel<<<final_blocks, TB>>>(uid, iid, out);
}

// round 2
// speedup vs baseline: 1.9358x; 1.9358x over previous
#include <cuda_runtime.h>
#include <cstdint>

#define NUM_USERS 100000
#define NUM_ITEMS 200000
#define N_TOTAL   300000
#define EMBED_DIM 64
#define NNZ       4000000
#define BATCH     16384

#define SCAN_B 1024
#define NB_SCAN ((N_TOTAL + SCAN_B - 1) / SCAN_B)   // 293

// Layer embeddings: x[0]=init, x[1..3]=layer outputs. 4 x 76.8MB.
__device__ float4 g_x[4][(size_t)N_TOTAL * 16];
// CSR build scratch
__device__ int  g_cnt[N_TOTAL];
__device__ int  g_off[N_TOTAL + 1];
__device__ int  g_cur[N_TOTAL];
__device__ int  g_bsum[NB_SCAN];
// Packed sorted edges: (col, val_bits), row-major order. 32MB.
__device__ int2 g_edges[NNZ];

// ---------------------------------------------------------------------------
// init: x[0] = concat(user_emb, item_emb); also zero histogram counters.
// ---------------------------------------------------------------------------
__global__ void init_kernel(const float4* __restrict__ uw,
                            const float4* __restrict__ iw) {
    int idx = blockIdx.x * blockDim.x + threadIdx.x;
    const int total = N_TOTAL * 16;
    if (idx < N_TOTAL) g_cnt[idx] = 0;
    if (idx >= total) return;
    int row = idx >> 4;
    float4 v = (row < NUM_USERS) ? uw[idx] : iw[idx - NUM_USERS * 16];
    g_x[0][idx] = v;
}

// ---------------------------------------------------------------------------
// histogram over destination rows
// ---------------------------------------------------------------------------
__global__ void hist_kernel(const int* __restrict__ rows) {
    int e = blockIdx.x * blockDim.x + threadIdx.x;
    if (e >= NNZ) return;
    atomicAdd(&g_cnt[__ldg(rows + e)], 1);
}

// ---------------------------------------------------------------------------
// 3-kernel exclusive scan of g_cnt -> g_off (off[0]=0, off[i+1]=incl[i])
// ---------------------------------------------------------------------------
__global__ void scan_local_kernel() {
    __shared__ int sh[SCAN_B];
    int gid = blockIdx.x * SCAN_B + threadIdx.x;
    int v = (gid < N_TOTAL) ? g_cnt[gid] : 0;
    sh[threadIdx.x] = v;
    __syncthreads();
    #pragma unroll
    for (int o = 1; o < SCAN_B; o <<= 1) {
        int t = (threadIdx.x >= o) ? sh[threadIdx.x - o] : 0;
        __syncthreads();
        sh[threadIdx.x] += t;
        __syncthreads();
    }
    if (gid < N_TOTAL) g_off[gid + 1] = sh[threadIdx.x];
    if (threadIdx.x == SCAN_B - 1) g_bsum[blockIdx.x] = sh[threadIdx.x];
}

__global__ void scan_bsum_kernel() {
    __shared__ int sh[512];
    int v = ((int)threadIdx.x < NB_SCAN) ? g_bsum[threadIdx.x] : 0;
    sh[threadIdx.x] = v;
    __syncthreads();
    #pragma unroll
    for (int o = 1; o < 512; o <<= 1) {
        int t = (threadIdx.x >= o) ? sh[threadIdx.x - o] : 0;
        __syncthreads();
        sh[threadIdx.x] += t;
        __syncthreads();
    }
    if ((int)threadIdx.x < NB_SCAN) g_bsum[threadIdx.x] = sh[threadIdx.x];
}

__global__ void scan_add_kernel() {
    int gid = blockIdx.x * blockDim.x + threadIdx.x;
    if (gid == 0) g_off[0] = 0;
    if (gid >= N_TOTAL) return;
    int b = gid / SCAN_B;
    if (b > 0) g_off[gid + 1] += g_bsum[b - 1];
    g_cur[gid] = 0;
}

// ---------------------------------------------------------------------------
// scatter edges into row-sorted packed array
// ---------------------------------------------------------------------------
__global__ void scatter_kernel(const int*   __restrict__ rows,
                               const int*   __restrict__ cols,
                               const float* __restrict__ vals) {
    int e = blockIdx.x * blockDim.x + threadIdx.x;
    if (e >= NNZ) return;
    int r = __ldg(rows + e);
    int pos = g_off[r] + atomicAdd(&g_cur[r], 1);
    __stcs(&g_edges[pos], make_int2(__ldg(cols + e),
                                    __float_as_int(__ldg(vals + e))));
}

// ---------------------------------------------------------------------------
// Pull-style CSR spmm: x[dst_l] = A * x[src_l].
// 16 threads per destination row, float4 accumulator per lane.
// Output written once via streaming store (keep L2 for the gather source).
// ---------------------------------------------------------------------------
__global__ void spmm_csr_kernel(int src_l, int dst_l) {
    int tid = blockIdx.x * blockDim.x + threadIdx.x;
    int row = tid >> 4;
    int c   = tid & 15;
    if (row >= N_TOTAL) return;

    const float4* __restrict__ src = g_x[src_l];
    float4*       __restrict__ dst = g_x[dst_l];

    int beg = __ldg(&g_off[row]);
    int end = __ldg(&g_off[row + 1]);

    float4 acc = make_float4(0.f, 0.f, 0.f, 0.f);
    int e = beg;
    // 2-wide unroll for memory-level parallelism on the random gathers
    for (; e + 1 < end; e += 2) {
        int2 p0 = __ldcs(&g_edges[e]);
        int2 p1 = __ldcs(&g_edges[e + 1]);
        float4 x0 = __ldg(src + ((size_t)p0.x * 16 + c));
        float4 x1 = __ldg(src + ((size_t)p1.x * 16 + c));
        float v0 = __int_as_float(p0.y);
        float v1 = __int_as_float(p1.y);
        acc.x += v0 * x0.x + v1 * x1.x;
        acc.y += v0 * x0.y + v1 * x1.y;
        acc.z += v0 * x0.z + v1 * x1.z;
        acc.w += v0 * x0.w + v1 * x1.w;
    }
    if (e < end) {
        int2 p = __ldcs(&g_edges[e]);
        float4 x = __ldg(src + ((size_t)p.x * 16 + c));
        float v = __int_as_float(p.y);
        acc.x += v * x.x; acc.y += v * x.y;
        acc.z += v * x.z; acc.w += v * x.w;
    }
    __stcs(dst + ((size_t)row * 16 + c), acc);
}

// ---------------------------------------------------------------------------
// final: out[b] = dot(sum_l x[l][u], sum_l x[l][i+NU]) / 16
// ---------------------------------------------------------------------------
__global__ void final_kernel(const int* __restrict__ uid,
                             const int* __restrict__ iid,
                             float* __restrict__ out) {
    int tid = blockIdx.x * blockDim.x + threadIdx.x;
    if (tid >= BATCH * 16) return;
    int b = tid >> 4;
    int c = tid & 15;

    size_t ui = (size_t)__ldg(uid + b) * 16 + c;
    size_t ii = (size_t)(__ldg(iid + b) + NUM_USERS) * 16 + c;

    float4 au = make_float4(0.f, 0.f, 0.f, 0.f);
    float4 ai = make_float4(0.f, 0.f, 0.f, 0.f);
    #pragma unroll
    for (int l = 0; l < 4; l++) {
        float4 xu = __ldg(&g_x[l][ui]);
        float4 xi = __ldg(&g_x[l][ii]);
        au.x += xu.x; au.y += xu.y; au.z += xu.z; au.w += xu.w;
        ai.x += xi.x; ai.y += xi.y; ai.z += xi.z; ai.w += xi.w;
    }
    float s = au.x * ai.x + au.y * ai.y + au.z * ai.z + au.w * ai.w;

    #pragma unroll
    for (int o = 8; o > 0; o >>= 1)
        s += __shfl_down_sync(0xffffffffu, s, o, 16);

    if (c == 0) out[b] = s * (1.0f / 16.0f);
}

// ---------------------------------------------------------------------------
// kernel_launch
// inputs: user_ids, item_ids, adj_row, adj_col, adj_val, user_emb_w, item_emb_w
// ---------------------------------------------------------------------------
extern "C" void kernel_launch(void* const* d_in, const int* in_sizes, int n_in,
                              void* d_out, int out_size) {
    const int*   uid  = (const int*)  d_in[0];
    const int*   iid  = (const int*)  d_in[1];
    const int*   rows = (const int*)  d_in[2];
    const int*   cols = (const int*)  d_in[3];
    const float* vals = (const float*)d_in[4];
    const float4* uw  = (const float4*)d_in[5];
    const float4* iw  = (const float4*)d_in[6];
    float* out = (float*)d_out;

    const int TB = 256;
    const int init_blocks  = (N_TOTAL * 16 + TB - 1) / TB;
    const int edge_blocks  = (NNZ + TB - 1) / TB;
    const int node_blocks  = (N_TOTAL + TB - 1) / TB;
    const int spmm_blocks  = (N_TOTAL * 16 + TB - 1) / TB;
    const int final_blocks = (BATCH * 16 + TB - 1) / TB;

    // x[0] = concat embeddings; zero histogram
    init_kernel<<<init_blocks, TB>>>(uw, iw);

    // build row-sorted CSR once (reused by all 3 layers)
    hist_kernel<<<edge_blocks, TB>>>(rows);
    scan_local_kernel<<<NB_SCAN, SCAN_B>>>();
    scan_bsum_kernel<<<1, 512>>>();
    scan_add_kernel<<<node_blocks, TB>>>();
    scatter_kernel<<<edge_blocks, TB>>>(rows, cols, vals);

    // 3 atomic-free SpMM layers
    spmm_csr_kernel<<<spmm_blocks, TB>>>(0, 1);
    spmm_csr_kernel<<<spmm_blocks, TB>>>(1, 2);
    spmm_csr_kernel<<<spmm_blocks, TB>>>(2, 3);

    final_kernel<<<final_blocks, TB>>>(uid, iid, out);
}

// round 3
// speedup vs baseline: 3.6381x; 1.8794x over previous
#include <cuda_runtime.h>
#include <cuda_fp16.h>
#include <cstdint>

#define NUM_USERS 100000
#define NUM_ITEMS 200000
#define N_TOTAL   300000
#define EMBED_DIM 64
#define NNZ       4000000
#define BATCH     16384

#define SCAN_B 1024
#define NB_SCAN ((N_TOTAL + SCAN_B - 1) / SCAN_B)   // 293

// Node features stored fp16: 64 halves = 8 uint4 per row. 38.4MB per layer.
__device__ uint4 g_xh[4][(size_t)N_TOTAL * 8];
// CSR build scratch
__device__ int  g_cnt[N_TOTAL];
__device__ int  g_off[N_TOTAL + 1];
__device__ int  g_cur[N_TOTAL];
__device__ int  g_bsum[NB_SCAN];
// Row-sorted packed edges: (col, val_bits). 32MB.
__device__ int2 g_edges[NNZ];

// ---------------------------------------------------------------------------
// init: x[0] = fp16(concat(user_emb, item_emb)); zero histogram.
// One thread per 8 floats (uint4 of halves).
// ---------------------------------------------------------------------------
__global__ void init_kernel(const float4* __restrict__ uw,
                            const float4* __restrict__ iw) {
    int idx = blockIdx.x * blockDim.x + threadIdx.x;
    if (idx < N_TOTAL) g_cnt[idx] = 0;
    const int total = N_TOTAL * 8;
    if (idx >= total) return;
    int row = idx >> 3;
    int c   = idx & 7;
    const float4* s = (row < NUM_USERS)
        ? (uw + (size_t)row * 16 + c * 2)
        : (iw + (size_t)(row - NUM_USERS) * 16 + c * 2);
    float4 f0 = __ldg(s);
    float4 f1 = __ldg(s + 1);
    uint4 o;
    __half2* oh = reinterpret_cast<__half2*>(&o);
    oh[0] = __float22half2_rn(make_float2(f0.x, f0.y));
    oh[1] = __float22half2_rn(make_float2(f0.z, f0.w));
    oh[2] = __float22half2_rn(make_float2(f1.x, f1.y));
    oh[3] = __float22half2_rn(make_float2(f1.z, f1.w));
    g_xh[0][idx] = o;
}

// ---------------------------------------------------------------------------
// histogram over destination rows
// ---------------------------------------------------------------------------
__global__ void hist_kernel(const int* __restrict__ rows) {
    int e = blockIdx.x * blockDim.x + threadIdx.x;
    if (e >= NNZ) return;
    atomicAdd(&g_cnt[__ldg(rows + e)], 1);
}

// ---------------------------------------------------------------------------
// 3-kernel exclusive scan of g_cnt -> g_off
// ---------------------------------------------------------------------------
__global__ void scan_local_kernel() {
    __shared__ int sh[SCAN_B];
    int gid = blockIdx.x * SCAN_B + threadIdx.x;
    int v = (gid < N_TOTAL) ? g_cnt[gid] : 0;
    sh[threadIdx.x] = v;
    __syncthreads();
    #pragma unroll
    for (int o = 1; o < SCAN_B; o <<= 1) {
        int t = (threadIdx.x >= o) ? sh[threadIdx.x - o] : 0;
        __syncthreads();
        sh[threadIdx.x] += t;
        __syncthreads();
    }
    if (gid < N_TOTAL) g_off[gid + 1] = sh[threadIdx.x];
    if (threadIdx.x == SCAN_B - 1) g_bsum[blockIdx.x] = sh[threadIdx.x];
}

__global__ void scan_bsum_kernel() {
    __shared__ int sh[512];
    int v = ((int)threadIdx.x < NB_SCAN) ? g_bsum[threadIdx.x] : 0;
    sh[threadIdx.x] = v;
    __syncthreads();
    #pragma unroll
    for (int o = 1; o < 512; o <<= 1) {
        int t = (threadIdx.x >= o) ? sh[threadIdx.x - o] : 0;
        __syncthreads();
        sh[threadIdx.x] += t;
        __syncthreads();
    }
    if ((int)threadIdx.x < NB_SCAN) g_bsum[threadIdx.x] = sh[threadIdx.x];
}

__global__ void scan_add_kernel() {
    int gid = blockIdx.x * blockDim.x + threadIdx.x;
    if (gid == 0) g_off[0] = 0;
    if (gid >= N_TOTAL) return;
    int b = gid / SCAN_B;
    if (b > 0) g_off[gid + 1] += g_bsum[b - 1];
    g_cur[gid] = 0;
}

// ---------------------------------------------------------------------------
// scatter edges into row-sorted packed array
// ---------------------------------------------------------------------------
__global__ void scatter_kernel(const int*   __restrict__ rows,
                               const int*   __restrict__ cols,
                               const float* __restrict__ vals) {
    int e = blockIdx.x * blockDim.x + threadIdx.x;
    if (e >= NNZ) return;
    int r = __ldg(rows + e);
    int pos = g_off[r] + atomicAdd(&g_cur[r], 1);
    __stcs(&g_edges[pos], make_int2(__ldg(cols + e),
                                    __float_as_int(__ldg(vals + e))));
}

// ---------------------------------------------------------------------------
// fp16 CSR spmm: 8 lanes per destination row, lane c handles dims [8c,8c+8).
// Gather uint4 (8 halves), accumulate fp32, convert+store once.
// ---------------------------------------------------------------------------
__device__ __forceinline__ void acc8(float2& a0, float2& a1,
                                     float2& a2, float2& a3,
                                     uint4 u, float v) {
    const __half2* h = reinterpret_cast<const __half2*>(&u);
    float2 f;
    f = __half22float2(h[0]); a0.x += v * f.x; a0.y += v * f.y;
    f = __half22float2(h[1]); a1.x += v * f.x; a1.y += v * f.y;
    f = __half22float2(h[2]); a2.x += v * f.x; a2.y += v * f.y;
    f = __half22float2(h[3]); a3.x += v * f.x; a3.y += v * f.y;
}

__global__ void spmm_csr_kernel(int src_l, int dst_l) {
    int tid = blockIdx.x * blockDim.x + threadIdx.x;
    int row = tid >> 3;
    int c   = tid & 7;
    if (row >= N_TOTAL) return;

    const uint4* __restrict__ src = g_xh[src_l];
    uint4*       __restrict__ dst = g_xh[dst_l];

    int beg = __ldg(&g_off[row]);
    int end = __ldg(&g_off[row + 1]);

    float2 a0 = {0.f, 0.f}, a1 = {0.f, 0.f}, a2 = {0.f, 0.f}, a3 = {0.f, 0.f};
    int e = beg;
    for (; e + 1 < end; e += 2) {
        int2 p0 = __ldcs(&g_edges[e]);
        int2 p1 = __ldcs(&g_edges[e + 1]);
        uint4 u0 = __ldg(src + ((size_t)p0.x * 8 + c));
        uint4 u1 = __ldg(src + ((size_t)p1.x * 8 + c));
        acc8(a0, a1, a2, a3, u0, __int_as_float(p0.y));
        acc8(a0, a1, a2, a3, u1, __int_as_float(p1.y));
    }
    if (e < end) {
        int2 p = __ldcs(&g_edges[e]);
        uint4 u = __ldg(src + ((size_t)p.x * 8 + c));
        acc8(a0, a1, a2, a3, u, __int_as_float(p.y));
    }

    uint4 o;
    __half2* oh = reinterpret_cast<__half2*>(&o);
    oh[0] = __float22half2_rn(a0);
    oh[1] = __float22half2_rn(a1);
    oh[2] = __float22half2_rn(a2);
    oh[3] = __float22half2_rn(a3);
    __stcs(dst + ((size_t)row * 8 + c), o);
}

// ---------------------------------------------------------------------------
// final: out[b] = dot(sum_l x[l][u], sum_l x[l][i+NU]) / 16
// 8 lanes per batch element.
// ---------------------------------------------------------------------------
__global__ void final_kernel(const int* __restrict__ uid,
                             const int* __restrict__ iid,
                             float* __restrict__ out) {
    int tid = blockIdx.x * blockDim.x + threadIdx.x;
    if (tid >= BATCH * 8) return;
    int b = tid >> 3;
    int c = tid & 7;

    size_t ui = (size_t)__ldg(uid + b) * 8 + c;
    size_t ii = (size_t)(__ldg(iid + b) + NUM_USERS) * 8 + c;

    float au[8] = {0, 0, 0, 0, 0, 0, 0, 0};
    float ai[8] = {0, 0, 0, 0, 0, 0, 0, 0};
    #pragma unroll
    for (int l = 0; l < 4; l++) {
        uint4 xu = __ldg(&g_xh[l][ui]);
        uint4 xi = __ldg(&g_xh[l][ii]);
        const __half2* hu = reinterpret_cast<const __half2*>(&xu);
        const __half2* hi = reinterpret_cast<const __half2*>(&xi);
        #pragma unroll
        for (int k = 0; k < 4; k++) {
            float2 fu = __half22float2(hu[k]);
            float2 fi = __half22float2(hi[k]);
            au[2 * k]     += fu.x;  au[2 * k + 1] += fu.y;
            ai[2 * k]     += fi.x;  ai[2 * k + 1] += fi.y;
        }
    }
    float s = 0.f;
    #pragma unroll
    for (int k = 0; k < 8; k++) s += au[k] * ai[k];

    #pragma unroll
    for (int o = 4; o > 0; o >>= 1)
        s += __shfl_down_sync(0xffffffffu, s, o, 8);

    if (c == 0) out[b] = s * (1.0f / 16.0f);
}

// ---------------------------------------------------------------------------
// kernel_launch
// inputs: user_ids, item_ids, adj_row, adj_col, adj_val, user_emb_w, item_emb_w
// ---------------------------------------------------------------------------
extern "C" void kernel_launch(void* const* d_in, const int* in_sizes, int n_in,
                              void* d_out, int out_size) {
    const int*   uid  = (const int*)  d_in[0];
    const int*   iid  = (const int*)  d_in[1];
    const int*   rows = (const int*)  d_in[2];
    const int*   cols = (const int*)  d_in[3];
    const float* vals = (const float*)d_in[4];
    const float4* uw  = (const float4*)d_in[5];
    const float4* iw  = (const float4*)d_in[6];
    float* out = (float*)d_out;

    const int TB = 256;
    const int init_blocks  = (N_TOTAL * 8 + TB - 1) / TB;
    const int edge_blocks  = (NNZ + TB - 1) / TB;
    const int node_blocks  = (N_TOTAL + TB - 1) / TB;
    const int spmm_blocks  = (N_TOTAL * 8 + TB - 1) / TB;
    const int final_blocks = (BATCH * 8 + TB - 1) / TB;

    init_kernel<<<init_blocks, TB>>>(uw, iw);

    hist_kernel<<<edge_blocks, TB>>>(rows);
    scan_local_kernel<<<NB_SCAN, SCAN_B>>>();
    scan_bsum_kernel<<<1, 512>>>();
    scan_add_kernel<<<node_blocks, TB>>>();
    scatter_kernel<<<edge_blocks, TB>>>(rows, cols, vals);

    spmm_csr_kernel<<<spmm_blocks, TB>>>(0, 1);
    spmm_csr_kernel<<<spmm_blocks, TB>>>(1, 2);
    spmm_csr_kernel<<<spmm_blocks, TB>>>(2, 3);

    final_kernel<<<final_blocks, TB>>>(uid, iid, out);
}

// round 4
// speedup vs baseline: 4.0948x; 1.1256x over previous
#include <cuda_runtime.h>
#include <cuda_fp16.h>
#include <cstdint>

#define NUM_USERS 100000
#define NUM_ITEMS 200000
#define N_TOTAL   300000
#define EMBED_DIM 64
#define NNZ       4000000
#define BATCH     16384

#define SCAN_B 1024
#define NB_SCAN ((N_TOTAL + SCAN_B - 1) / SCAN_B)   // 293

// Node features fp16: 64 halves = 8 uint4 per row. 38.4MB per buffer.
// [0]=x0, [1]=x1, [2]=x2, [3]=s = x0+x1+x2
__device__ uint4 g_xh[4][(size_t)N_TOTAL * 8];
// CSR build scratch
__device__ int  g_cnt[N_TOTAL];
__device__ int  g_off[N_TOTAL + 1];
__device__ int  g_cur[N_TOTAL];
__device__ int  g_bsum[NB_SCAN];
// Row-sorted packed edges: (col, val_bits). 32MB.
__device__ int2 g_edges[NNZ];

// ---------------------------------------------------------------------------
// init + hist fused: x[0] = fp16(concat(embs)); zero g_cnt; histogram rows.
// Grid covers max(N_TOTAL*8, NNZ) threads.
// ---------------------------------------------------------------------------
__global__ void init_hist_kernel(const float4* __restrict__ uw,
                                 const float4* __restrict__ iw,
                                 const int*    __restrict__ rows) {
    int idx = blockIdx.x * blockDim.x + threadIdx.x;

    if (idx < N_TOTAL * 8) {
        int row = idx >> 3;
        int c   = idx & 7;
        const float4* s = (row < NUM_USERS)
            ? (uw + (size_t)row * 16 + c * 2)
            : (iw + (size_t)(row - NUM_USERS) * 16 + c * 2);
        float4 f0 = __ldg(s);
        float4 f1 = __ldg(s + 1);
        uint4 o;
        __half2* oh = reinterpret_cast<__half2*>(&o);
        oh[0] = __float22half2_rn(make_float2(f0.x, f0.y));
        oh[1] = __float22half2_rn(make_float2(f0.z, f0.w));
        oh[2] = __float22half2_rn(make_float2(f1.x, f1.y));
        oh[3] = __float22half2_rn(make_float2(f1.z, f1.w));
        g_xh[0][idx] = o;
    }
    if (idx < NNZ) {
        atomicAdd(&g_cnt[__ldg(rows + idx)], 1);
    }
}

// g_cnt must be zero before init_hist; zero it in a tiny preceding kernel.
__global__ void zero_cnt_kernel() {
    int idx = blockIdx.x * blockDim.x + threadIdx.x;
    if (idx < N_TOTAL) g_cnt[idx] = 0;
}

// ---------------------------------------------------------------------------
// 3-kernel exclusive scan of g_cnt -> g_off
// ---------------------------------------------------------------------------
__global__ void scan_local_kernel() {
    __shared__ int sh[SCAN_B];
    int gid = blockIdx.x * SCAN_B + threadIdx.x;
    int v = (gid < N_TOTAL) ? g_cnt[gid] : 0;
    sh[threadIdx.x] = v;
    __syncthreads();
    #pragma unroll
    for (int o = 1; o < SCAN_B; o <<= 1) {
        int t = (threadIdx.x >= o) ? sh[threadIdx.x - o] : 0;
        __syncthreads();
        sh[threadIdx.x] += t;
        __syncthreads();
    }
    if (gid < N_TOTAL) g_off[gid + 1] = sh[threadIdx.x];
    if (threadIdx.x == SCAN_B - 1) g_bsum[blockIdx.x] = sh[threadIdx.x];
}

__global__ void scan_bsum_kernel() {
    __shared__ int sh[512];
    int v = ((int)threadIdx.x < NB_SCAN) ? g_bsum[threadIdx.x] : 0;
    sh[threadIdx.x] = v;
    __syncthreads();
    #pragma unroll
    for (int o = 1; o < 512; o <<= 1) {
        int t = (threadIdx.x >= o) ? sh[threadIdx.x - o] : 0;
        __syncthreads();
        sh[threadIdx.x] += t;
        __syncthreads();
    }
    if ((int)threadIdx.x < NB_SCAN) g_bsum[threadIdx.x] = sh[threadIdx.x];
}

__global__ void scan_add_kernel() {
    int gid = blockIdx.x * blockDim.x + threadIdx.x;
    if (gid == 0) g_off[0] = 0;
    if (gid >= N_TOTAL) return;
    int b = gid / SCAN_B;
    if (b > 0) g_off[gid + 1] += g_bsum[b - 1];
    g_cur[gid] = 0;
}

// ---------------------------------------------------------------------------
// scatter edges into row-sorted packed array
// ---------------------------------------------------------------------------
__global__ void scatter_kernel(const int*   __restrict__ rows,
                               const int*   __restrict__ cols,
                               const float* __restrict__ vals) {
    int e = blockIdx.x * blockDim.x + threadIdx.x;
    if (e >= NNZ) return;
    int r = __ldg(rows + e);
    int pos = g_off[r] + atomicAdd(&g_cur[r], 1);
    __stcs(&g_edges[pos], make_int2(__ldg(cols + e),
                                    __float_as_int(__ldg(vals + e))));
}

// ---------------------------------------------------------------------------
// fp16 CSR spmm: 8 lanes per destination row, lane c handles dims [8c,8c+8).
// FUSE_SUM: also write s = x0[row] + x1[row] + acc  (used on the x1->x2 pass)
// ---------------------------------------------------------------------------
__device__ __forceinline__ void acc8(float2& a0, float2& a1,
                                     float2& a2, float2& a3,
                                     uint4 u, float v) {
    const __half2* h = reinterpret_cast<const __half2*>(&u);
    float2 f;
    f = __half22float2(h[0]); a0.x += v * f.x; a0.y += v * f.y;
    f = __half22float2(h[1]); a1.x += v * f.x; a1.y += v * f.y;
    f = __half22float2(h[2]); a2.x += v * f.x; a2.y += v * f.y;
    f = __half22float2(h[3]); a3.x += v * f.x; a3.y += v * f.y;
}

__device__ __forceinline__ void add8(float2& a0, float2& a1,
                                     float2& a2, float2& a3, uint4 u) {
    const __half2* h = reinterpret_cast<const __half2*>(&u);
    float2 f;
    f = __half22float2(h[0]); a0.x += f.x; a0.y += f.y;
    f = __half22float2(h[1]); a1.x += f.x; a1.y += f.y;
    f = __half22float2(h[2]); a2.x += f.x; a2.y += f.y;
    f = __half22float2(h[3]); a3.x += f.x; a3.y += f.y;
}

__device__ __forceinline__ uint4 pack8(float2 a0, float2 a1,
                                       float2 a2, float2 a3) {
    uint4 o;
    __half2* oh = reinterpret_cast<__half2*>(&o);
    oh[0] = __float22half2_rn(a0);
    oh[1] = __float22half2_rn(a1);
    oh[2] = __float22half2_rn(a2);
    oh[3] = __float22half2_rn(a3);
    return o;
}

template <bool FUSE_SUM>
__global__ void spmm_csr_kernel(int src_l, int dst_l) {
    int tid = blockIdx.x * blockDim.x + threadIdx.x;
    int row = tid >> 3;
    int c   = tid & 7;
    if (row >= N_TOTAL) return;

    const uint4* __restrict__ src = g_xh[src_l];
    uint4*       __restrict__ dst = g_xh[dst_l];

    int beg = __ldg(&g_off[row]);
    int end = __ldg(&g_off[row + 1]);

    float2 a0 = {0.f, 0.f}, a1 = {0.f, 0.f}, a2 = {0.f, 0.f}, a3 = {0.f, 0.f};
    int e = beg;
    for (; e + 1 < end; e += 2) {
        int2 p0 = __ldcs(&g_edges[e]);
        int2 p1 = __ldcs(&g_edges[e + 1]);
        uint4 u0 = __ldg(src + ((size_t)p0.x * 8 + c));
        uint4 u1 = __ldg(src + ((size_t)p1.x * 8 + c));
        acc8(a0, a1, a2, a3, u0, __int_as_float(p0.y));
        acc8(a0, a1, a2, a3, u1, __int_as_float(p1.y));
    }
    if (e < end) {
        int2 p = __ldcs(&g_edges[e]);
        uint4 u = __ldg(src + ((size_t)p.x * 8 + c));
        acc8(a0, a1, a2, a3, u, __int_as_float(p.y));
    }

    size_t oidx = (size_t)row * 8 + c;
    __stcs(dst + oidx, pack8(a0, a1, a2, a3));

    if (FUSE_SUM) {
        // s = x0 + x1 + x2 ; src here is x1
        add8(a0, a1, a2, a3, __ldg(&g_xh[0][oidx]));
        add8(a0, a1, a2, a3, __ldg(src + oidx));
        __stcs(&g_xh[3][oidx], pack8(a0, a1, a2, a3));
    }
}

// ---------------------------------------------------------------------------
// final: per batch element, compute layer-3 rows u and i on the fly from x2,
// add s, dot, scale. 8 lanes per batch element; lane c owns dims [8c, 8c+8).
// ---------------------------------------------------------------------------
__global__ void final_kernel(const int* __restrict__ uid,
                             const int* __restrict__ iid,
                             float* __restrict__ out) {
    int tid = blockIdx.x * blockDim.x + threadIdx.x;
    if (tid >= BATCH * 8) return;
    int b = tid >> 3;
    int c = tid & 7;

    int ru = __ldg(uid + b);
    int ri = __ldg(iid + b) + NUM_USERS;

    const uint4* __restrict__ x2 = g_xh[2];

    float fu[8], fi[8];
    {   // s rows
        uint4 su = __ldg(&g_xh[3][(size_t)ru * 8 + c]);
        uint4 si = __ldg(&g_xh[3][(size_t)ri * 8 + c]);
        const __half2* hu = reinterpret_cast<const __half2*>(&su);
        const __half2* hi = reinterpret_cast<const __half2*>(&si);
        #pragma unroll
        for (int k = 0; k < 4; k++) {
            float2 f = __half22float2(hu[k]);
            fu[2 * k] = f.x; fu[2 * k + 1] = f.y;
            f = __half22float2(hi[k]);
            fi[2 * k] = f.x; fi[2 * k + 1] = f.y;
        }
    }

    // layer-3 row u
    {
        int beg = __ldg(&g_off[ru]);
        int end = __ldg(&g_off[ru + 1]);
        for (int e = beg; e < end; e++) {
            int2 p = __ldg(&g_edges[e]);
            uint4 u = __ldg(x2 + ((size_t)p.x * 8 + c));
            float v = __int_as_float(p.y);
            const __half2* h = reinterpret_cast<const __half2*>(&u);
            #pragma unroll
            for (int k = 0; k < 4; k++) {
                float2 f = __half22float2(h[k]);
                fu[2 * k]     += v * f.x;
                fu[2 * k + 1] += v * f.y;
            }
        }
    }
    // layer-3 row i
    {
        int beg = __ldg(&g_off[ri]);
        int end = __ldg(&g_off[ri + 1]);
        for (int e = beg; e < end; e++) {
            int2 p = __ldg(&g_edges[e]);
            uint4 u = __ldg(x2 + ((size_t)p.x * 8 + c));
            float v = __int_as_float(p.y);
            const __half2* h = reinterpret_cast<const __half2*>(&u);
            #pragma unroll
            for (int k = 0; k < 4; k++) {
                float2 f = __half22float2(h[k]);
                fi[2 * k]     += v * f.x;
                fi[2 * k + 1] += v * f.y;
            }
        }
    }

    float s = 0.f;
    #pragma unroll
    for (int k = 0; k < 8; k++) s += fu[k] * fi[k];

    #pragma unroll
    for (int o = 4; o > 0; o >>= 1)
        s += __shfl_down_sync(0xffffffffu, s, o, 8);

    if (c == 0) out[b] = s * (1.0f / 16.0f);
}

// ---------------------------------------------------------------------------
// kernel_launch
// inputs: user_ids, item_ids, adj_row, adj_col, adj_val, user_emb_w, item_emb_w
// ---------------------------------------------------------------------------
extern "C" void kernel_launch(void* const* d_in, const int* in_sizes, int n_in,
                              void* d_out, int out_size) {
    const int*   uid  = (const int*)  d_in[0];
    const int*   iid  = (const int*)  d_in[1];
    const int*   rows = (const int*)  d_in[2];
    const int*   cols = (const int*)  d_in[3];
    const float* vals = (const float*)d_in[4];
    const float4* uw  = (const float4*)d_in[5];
    const float4* iw  = (const float4*)d_in[6];
    float* out = (float*)d_out;

    const int TB = 256;
    const int ih_threads   = (NNZ > N_TOTAL * 8) ? NNZ : N_TOTAL * 8;
    const int ih_blocks    = (ih_threads + TB - 1) / TB;
    const int zero_blocks  = (N_TOTAL + TB - 1) / TB;
    const int edge_blocks  = (NNZ + TB - 1) / TB;
    const int node_blocks  = (N_TOTAL + TB - 1) / TB;
    const int spmm_blocks  = (N_TOTAL * 8 + TB - 1) / TB;
    const int final_blocks = (BATCH * 8 + TB - 1) / TB;

    zero_cnt_kernel<<<zero_blocks, TB>>>();
    init_hist_kernel<<<ih_blocks, TB>>>(uw, iw, rows);

    scan_local_kernel<<<NB_SCAN, SCAN_B>>>();
    scan_bsum_kernel<<<1, 512>>>();
    scan_add_kernel<<<node_blocks, TB>>>();
    scatter_kernel<<<edge_blocks, TB>>>(rows, cols, vals);

    spmm_csr_kernel<false><<<spmm_blocks, TB>>>(0, 1);          // x1 = A x0
    spmm_csr_kernel<true ><<<spmm_blocks, TB>>>(1, 2);          // x2 = A x1, s = x0+x1+x2

    final_kernel<<<final_blocks, TB>>>(uid, iid, out);
}

// round 5
// speedup vs baseline: 4.1971x; 1.0250x over previous
#include <cuda_runtime.h>
#include <cuda_fp16.h>
#include <cstdint>

#define NUM_USERS 100000
#define NUM_ITEMS 200000
#define N_TOTAL   300000
#define EMBED_DIM 64
#define NNZ       4000000
#define BATCH     16384

#define SCAN_B 1024
#define NB_SCAN ((N_TOTAL + SCAN_B - 1) / SCAN_B)   // 293

// Node features fp16: 64 halves = 8 uint4 per row. 38.4MB per buffer.
// [0]=x0, [1]=x1, [2]=x2, [3]=s = x0+x1+x2
__device__ uint4 g_xh[4][(size_t)N_TOTAL * 8];
// CSR build scratch
__device__ int  g_cnt[N_TOTAL];
__device__ int  g_off[N_TOTAL + 1];
__device__ int  g_cur[N_TOTAL];
__device__ int  g_bsum[NB_SCAN];
// Row-sorted packed edges: (col, val_bits). 32MB.
__device__ int2 g_edges[NNZ];

// ---------------------------------------------------------------------------
// zero: g_cnt and g_cur (both consumed later in this graph iteration)
// ---------------------------------------------------------------------------
__global__ void zero_kernel() {
    int idx = blockIdx.x * blockDim.x + threadIdx.x;
    if (idx < N_TOTAL) { g_cnt[idx] = 0; g_cur[idx] = 0; }
}

// ---------------------------------------------------------------------------
// histogram over destination rows
// ---------------------------------------------------------------------------
__global__ void hist_kernel(const int* __restrict__ rows) {
    int e = blockIdx.x * blockDim.x + threadIdx.x;
    if (e >= NNZ) return;
    atomicAdd(&g_cnt[__ldg(rows + e)], 1);
}

// ---------------------------------------------------------------------------
// scan step 1: per-block inclusive scan of g_cnt, publish block sums
// ---------------------------------------------------------------------------
__global__ void scan_local_kernel() {
    __shared__ int sh[SCAN_B];
    int gid = blockIdx.x * SCAN_B + threadIdx.x;
    int v = (gid < N_TOTAL) ? g_cnt[gid] : 0;
    sh[threadIdx.x] = v;
    __syncthreads();
    #pragma unroll
    for (int o = 1; o < SCAN_B; o <<= 1) {
        int t = (threadIdx.x >= o) ? sh[threadIdx.x - o] : 0;
        __syncthreads();
        sh[threadIdx.x] += t;
        __syncthreads();
    }
    if (gid < N_TOTAL) g_off[gid + 1] = sh[threadIdx.x];
    if (threadIdx.x == SCAN_B - 1) g_bsum[blockIdx.x] = sh[threadIdx.x];
}

// ---------------------------------------------------------------------------
// scan step 2: every block redundantly scans the 293 block sums in smem,
// then adds its exclusive block prefix to its g_off range. No global sync
// tricks needed; 293 extra loads per block are trivial.
// ---------------------------------------------------------------------------
__global__ void scan_add2_kernel() {
    __shared__ int sh[SCAN_B];
    int t = threadIdx.x;
    sh[t] = (t < NB_SCAN) ? g_bsum[t] : 0;
    __syncthreads();
    #pragma unroll
    for (int o = 1; o < SCAN_B; o <<= 1) {
        int v = (t >= o) ? sh[t - o] : 0;
        __syncthreads();
        sh[t] += v;
        __syncthreads();
    }
    int prev = (blockIdx.x > 0) ? sh[blockIdx.x - 1] : 0;

    int gid = blockIdx.x * SCAN_B + t;
    if (gid == 0) g_off[0] = 0;
    if (gid < N_TOTAL) g_off[gid + 1] += prev;
}

// ---------------------------------------------------------------------------
// scatter + init fused:
//   idx < NNZ        : place edge e into its row-sorted slot
//   idx < N_TOTAL*8  : x0[idx] = fp16(concat(user_emb, item_emb))
// The x0 init (DRAM-heavy) overlaps the scatter (L2/latency-heavy).
// ---------------------------------------------------------------------------
__global__ void scatter_init_kernel(const int*   __restrict__ rows,
                                    const int*   __restrict__ cols,
                                    const float* __restrict__ vals,
                                    const float4* __restrict__ uw,
                                    const float4* __restrict__ iw) {
    int idx = blockIdx.x * blockDim.x + threadIdx.x;

    if (idx < NNZ) {
        int r = __ldg(rows + idx);
        int pos = __ldg(&g_off[r]) + atomicAdd(&g_cur[r], 1);
        __stcs(&g_edges[pos], make_int2(__ldg(cols + idx),
                                        __float_as_int(__ldg(vals + idx))));
    }
    if (idx < N_TOTAL * 8) {
        int row = idx >> 3;
        int c   = idx & 7;
        const float4* s = (row < NUM_USERS)
            ? (uw + (size_t)row * 16 + c * 2)
            : (iw + (size_t)(row - NUM_USERS) * 16 + c * 2);
        float4 f0 = __ldg(s);
        float4 f1 = __ldg(s + 1);
        uint4 o;
        __half2* oh = reinterpret_cast<__half2*>(&o);
        oh[0] = __float22half2_rn(make_float2(f0.x, f0.y));
        oh[1] = __float22half2_rn(make_float2(f0.z, f0.w));
        oh[2] = __float22half2_rn(make_float2(f1.x, f1.y));
        oh[3] = __float22half2_rn(make_float2(f1.z, f1.w));
        g_xh[0][idx] = o;
    }
}

// ---------------------------------------------------------------------------
// fp16 CSR spmm: 8 lanes per destination row, lane c handles dims [8c,8c+8).
// 4-edge unroll for memory-level parallelism on the random gathers.
// FUSE_SUM: also write s = x0[row] + x1[row] + acc (on the x1->x2 pass)
// ---------------------------------------------------------------------------
__device__ __forceinline__ void acc8(float2& a0, float2& a1,
                                     float2& a2, float2& a3,
                                     uint4 u, float v) {
    const __half2* h = reinterpret_cast<const __half2*>(&u);
    float2 f;
    f = __half22float2(h[0]); a0.x += v * f.x; a0.y += v * f.y;
    f = __half22float2(h[1]); a1.x += v * f.x; a1.y += v * f.y;
    f = __half22float2(h[2]); a2.x += v * f.x; a2.y += v * f.y;
    f = __half22float2(h[3]); a3.x += v * f.x; a3.y += v * f.y;
}

__device__ __forceinline__ void add8(float2& a0, float2& a1,
                                     float2& a2, float2& a3, uint4 u) {
    const __half2* h = reinterpret_cast<const __half2*>(&u);
    float2 f;
    f = __half22float2(h[0]); a0.x += f.x; a0.y += f.y;
    f = __half22float2(h[1]); a1.x += f.x; a1.y += f.y;
    f = __half22float2(h[2]); a2.x += f.x; a2.y += f.y;
    f = __half22float2(h[3]); a3.x += f.x; a3.y += f.y;
}

__device__ __forceinline__ uint4 pack8(float2 a0, float2 a1,
                                       float2 a2, float2 a3) {
    uint4 o;
    __half2* oh = reinterpret_cast<__half2*>(&o);
    oh[0] = __float22half2_rn(a0);
    oh[1] = __float22half2_rn(a1);
    oh[2] = __float22half2_rn(a2);
    oh[3] = __float22half2_rn(a3);
    return o;
}

template <bool FUSE_SUM>
__global__ void spmm_csr_kernel(int src_l, int dst_l) {
    int tid = blockIdx.x * blockDim.x + threadIdx.x;
    int row = tid >> 3;
    int c   = tid & 7;
    if (row >= N_TOTAL) return;

    const uint4* __restrict__ src = g_xh[src_l];
    uint4*       __restrict__ dst = g_xh[dst_l];

    int beg = __ldg(&g_off[row]);
    int end = __ldg(&g_off[row + 1]);

    float2 a0 = {0.f, 0.f}, a1 = {0.f, 0.f}, a2 = {0.f, 0.f}, a3 = {0.f, 0.f};
    int e = beg;
    for (; e + 3 < end; e += 4) {
        int2 p0 = __ldcs(&g_edges[e]);
        int2 p1 = __ldcs(&g_edges[e + 1]);
        int2 p2 = __ldcs(&g_edges[e + 2]);
        int2 p3 = __ldcs(&g_edges[e + 3]);
        uint4 u0 = __ldg(src + ((size_t)p0.x * 8 + c));
        uint4 u1 = __ldg(src + ((size_t)p1.x * 8 + c));
        uint4 u2 = __ldg(src + ((size_t)p2.x * 8 + c));
        uint4 u3 = __ldg(src + ((size_t)p3.x * 8 + c));
        acc8(a0, a1, a2, a3, u0, __int_as_float(p0.y));
        acc8(a0, a1, a2, a3, u1, __int_as_float(p1.y));
        acc8(a0, a1, a2, a3, u2, __int_as_float(p2.y));
        acc8(a0, a1, a2, a3, u3, __int_as_float(p3.y));
    }
    for (; e < end; e++) {
        int2 p = __ldcs(&g_edges[e]);
        uint4 u = __ldg(src + ((size_t)p.x * 8 + c));
        acc8(a0, a1, a2, a3, u, __int_as_float(p.y));
    }

    size_t oidx = (size_t)row * 8 + c;
    __stcs(dst + oidx, pack8(a0, a1, a2, a3));

    if (FUSE_SUM) {
        // s = x0 + x1 + x2 ; src here is x1
        add8(a0, a1, a2, a3, __ldg(&g_xh[0][oidx]));
        add8(a0, a1, a2, a3, __ldg(src + oidx));
        __stcs(&g_xh[3][oidx], pack8(a0, a1, a2, a3));
    }
}

// ---------------------------------------------------------------------------
// final: per batch element, compute layer-3 rows u and i on the fly from x2,
// add s, dot, scale. 8 lanes per batch element; lane c owns dims [8c, 8c+8).
// ---------------------------------------------------------------------------
__global__ void final_kernel(const int* __restrict__ uid,
                             const int* __restrict__ iid,
                             float* __restrict__ out) {
    int tid = blockIdx.x * blockDim.x + threadIdx.x;
    if (tid >= BATCH * 8) return;
    int b = tid >> 3;
    int c = tid & 7;

    int ru = __ldg(uid + b);
    int ri = __ldg(iid + b) + NUM_USERS;

    const uint4* __restrict__ x2 = g_xh[2];

    float fu[8], fi[8];
    {   // s rows
        uint4 su = __ldg(&g_xh[3][(size_t)ru * 8 + c]);
        uint4 si = __ldg(&g_xh[3][(size_t)ri * 8 + c]);
        const __half2* hu = reinterpret_cast<const __half2*>(&su);
        const __half2* hi = reinterpret_cast<const __half2*>(&si);
        #pragma unroll
        for (int k = 0; k < 4; k++) {
            float2 f = __half22float2(hu[k]);
            fu[2 * k] = f.x; fu[2 * k + 1] = f.y;
            f = __half22float2(hi[k]);
            fi[2 * k] = f.x; fi[2 * k + 1] = f.y;
        }
    }

    // layer-3 row u
    {
        int beg = __ldg(&g_off[ru]);
        int end = __ldg(&g_off[ru + 1]);
        for (int e = beg; e < end; e++) {
            int2 p = __ldg(&g_edges[e]);
            uint4 u = __ldg(x2 + ((size_t)p.x * 8 + c));
            float v = __int_as_float(p.y);
            const __half2* h = reinterpret_cast<const __half2*>(&u);
            #pragma unroll
            for (int k = 0; k < 4; k++) {
                float2 f = __half22float2(h[k]);
                fu[2 * k]     += v * f.x;
                fu[2 * k + 1] += v * f.y;
            }
        }
    }
    // layer-3 row i
    {
        int beg = __ldg(&g_off[ri]);
        int end = __ldg(&g_off[ri + 1]);
        for (int e = beg; e < end; e++) {
            int2 p = __ldg(&g_edges[e]);
            uint4 u = __ldg(x2 + ((size_t)p.x * 8 + c));
            float v = __int_as_float(p.y);
            const __half2* h = reinterpret_cast<const __half2*>(&u);
            #pragma unroll
            for (int k = 0; k < 4; k++) {
                float2 f = __half22float2(h[k]);
                fi[2 * k]     += v * f.x;
                fi[2 * k + 1] += v * f.y;
            }
        }
    }

    float s = 0.f;
    #pragma unroll
    for (int k = 0; k < 8; k++) s += fu[k] * fi[k];

    #pragma unroll
    for (int o = 4; o > 0; o >>= 1)
        s += __shfl_down_sync(0xffffffffu, s, o, 8);

    if (c == 0) out[b] = s * (1.0f / 16.0f);
}

// ---------------------------------------------------------------------------
// kernel_launch
// inputs: user_ids, item_ids, adj_row, adj_col, adj_val, user_emb_w, item_emb_w
// ---------------------------------------------------------------------------
extern "C" void kernel_launch(void* const* d_in, const int* in_sizes, int n_in,
                              void* d_out, int out_size) {
    const int*   uid  = (const int*)  d_in[0];
    const int*   iid  = (const int*)  d_in[1];
    const int*   rows = (const int*)  d_in[2];
    const int*   cols = (const int*)  d_in[3];
    const float* vals = (const float*)d_in[4];
    const float4* uw  = (const float4*)d_in[5];
    const float4* iw  = (const float4*)d_in[6];
    float* out = (float*)d_out;

    const int TB = 256;
    const int zero_blocks  = (N_TOTAL + TB - 1) / TB;
    const int edge_blocks  = (NNZ + TB - 1) / TB;
    const int si_threads   = (NNZ > N_TOTAL * 8) ? NNZ : N_TOTAL * 8;
    const int si_blocks    = (si_threads + TB - 1) / TB;
    const int spmm_blocks  = (N_TOTAL * 8 + TB - 1) / TB;
    const int final_blocks = (BATCH * 8 + TB - 1) / TB;

    zero_kernel<<<zero_blocks, TB>>>();
    hist_kernel<<<edge_blocks, TB>>>(rows);
    scan_local_kernel<<<NB_SCAN, SCAN_B>>>();
    scan_add2_kernel<<<NB_SCAN, SCAN_B>>>();
    scatter_init_kernel<<<si_blocks, TB>>>(rows, cols, vals, uw, iw);

    spmm_csr_kernel<false><<<spmm_blocks, TB>>>(0, 1);   // x1 = A x0
    spmm_csr_kernel<true ><<<spmm_blocks, TB>>>(1, 2);   // x2 = A x1, s = x0+x1+x2

    final_kernel<<<final_blocks, TB>>>(uid, iid, out);
}

// round 6
// speedup vs baseline: 4.3330x; 1.0324x over previous
#include <cuda_runtime.h>
#include <cuda_fp16.h>
#include <cstdint>

#define NUM_USERS 100000
#define NUM_ITEMS 200000
#define N_TOTAL   300000
#define EMBED_DIM 64
#define NNZ       4000000
#define BATCH     16384

#define SCAN_B 1024
#define NB_SCAN ((N_TOTAL + SCAN_B - 1) / SCAN_B)   // 293

// Node features fp16: 64 halves = 8 uint4 per row. 38.4MB per buffer.
// [0]=x0, [1]=x1, [2]=x2, [3]=s = x0+x1+x2
__device__ uint4 g_xh[4][(size_t)N_TOTAL * 8];
// CSR build scratch. NOTE: zero-initialized at module load; kernels below
// are self-cleaning (each graph replay leaves g_cnt/g_cur zeroed again),
// so no explicit zero pass is needed.
__device__ int  g_cnt[N_TOTAL];
__device__ int  g_off[N_TOTAL + 1];
__device__ int  g_cur[N_TOTAL];
__device__ int  g_bsum[NB_SCAN];
// Row-sorted packed edges: (col, val_bits). 32MB.
__device__ int2 g_edges[NNZ];

// ---------------------------------------------------------------------------
// histogram over destination rows (g_cnt starts at zero — see note above)
// ---------------------------------------------------------------------------
__global__ void hist_kernel(const int* __restrict__ rows) {
    int e = blockIdx.x * blockDim.x + threadIdx.x;
    if (e >= NNZ) return;
    atomicAdd(&g_cnt[__ldg(rows + e)], 1);
}

// ---------------------------------------------------------------------------
// scan step 1: per-block inclusive scan of g_cnt, publish block sums.
// Also RESETS g_cnt to zero (consumed exactly once -> self-cleaning for the
// next graph replay).
// ---------------------------------------------------------------------------
__global__ void scan_local_kernel() {
    __shared__ int sh[SCAN_B];
    int gid = blockIdx.x * SCAN_B + threadIdx.x;
    int v = 0;
    if (gid < N_TOTAL) {
        v = g_cnt[gid];
        g_cnt[gid] = 0;
    }
    sh[threadIdx.x] = v;
    __syncthreads();
    #pragma unroll
    for (int o = 1; o < SCAN_B; o <<= 1) {
        int t = (threadIdx.x >= o) ? sh[threadIdx.x - o] : 0;
        __syncthreads();
        sh[threadIdx.x] += t;
        __syncthreads();
    }
    if (gid < N_TOTAL) g_off[gid + 1] = sh[threadIdx.x];
    if (threadIdx.x == SCAN_B - 1) g_bsum[blockIdx.x] = sh[threadIdx.x];
}

// ---------------------------------------------------------------------------
// scan step 2: every block redundantly scans the 293 block sums in smem,
// then adds its exclusive block prefix to its g_off range. Also zeroes
// g_cur for the scatter that follows.
// ---------------------------------------------------------------------------
__global__ void scan_add2_kernel() {
    __shared__ int sh[SCAN_B];
    int t = threadIdx.x;
    sh[t] = (t < NB_SCAN) ? g_bsum[t] : 0;
    __syncthreads();
    #pragma unroll
    for (int o = 1; o < SCAN_B; o <<= 1) {
        int v = (t >= o) ? sh[t - o] : 0;
        __syncthreads();
        sh[t] += v;
        __syncthreads();
    }
    int prev = (blockIdx.x > 0) ? sh[blockIdx.x - 1] : 0;

    int gid = blockIdx.x * SCAN_B + t;
    if (gid == 0) g_off[0] = 0;
    if (gid < N_TOTAL) {
        g_off[gid + 1] += prev;
        g_cur[gid] = 0;
    }
}

// ---------------------------------------------------------------------------
// scatter + init fused:
//   idx < NNZ        : place edge e into its row-sorted slot (write-back
//                      store so edges stay L2-resident for spmm1)
//   idx < N_TOTAL*8  : x0[idx] = fp16(concat(user_emb, item_emb))
// ---------------------------------------------------------------------------
__global__ void scatter_init_kernel(const int*   __restrict__ rows,
                                    const int*   __restrict__ cols,
                                    const float* __restrict__ vals,
                                    const float4* __restrict__ uw,
                                    const float4* __restrict__ iw) {
    int idx = blockIdx.x * blockDim.x + threadIdx.x;

    if (idx < NNZ) {
        int r = __ldg(rows + idx);
        int pos = __ldg(&g_off[r]) + atomicAdd(&g_cur[r], 1);
        g_edges[pos] = make_int2(__ldg(cols + idx),
                                 __float_as_int(__ldg(vals + idx)));
    }
    if (idx < N_TOTAL * 8) {
        int row = idx >> 3;
        int c   = idx & 7;
        const float4* s = (row < NUM_USERS)
            ? (uw + (size_t)row * 16 + c * 2)
            : (iw + (size_t)(row - NUM_USERS) * 16 + c * 2);
        float4 f0 = __ldg(s);
        float4 f1 = __ldg(s + 1);
        uint4 o;
        __half2* oh = reinterpret_cast<__half2*>(&o);
        oh[0] = __float22half2_rn(make_float2(f0.x, f0.y));
        oh[1] = __float22half2_rn(make_float2(f0.z, f0.w));
        oh[2] = __float22half2_rn(make_float2(f1.x, f1.y));
        oh[3] = __float22half2_rn(make_float2(f1.z, f1.w));
        g_xh[0][idx] = o;
    }
}

// ---------------------------------------------------------------------------
// fp16 CSR spmm: 8 lanes per destination row, lane c handles dims [8c,8c+8).
// 4-edge unroll for memory-level parallelism on the random gathers.
// FUSE_SUM: also write s = x0[row] + x1[row] + acc (on the x1->x2 pass)
// ---------------------------------------------------------------------------
__device__ __forceinline__ void acc8(float2& a0, float2& a1,
                                     float2& a2, float2& a3,
                                     uint4 u, float v) {
    const __half2* h = reinterpret_cast<const __half2*>(&u);
    float2 f;
    f = __half22float2(h[0]); a0.x += v * f.x; a0.y += v * f.y;
    f = __half22float2(h[1]); a1.x += v * f.x; a1.y += v * f.y;
    f = __half22float2(h[2]); a2.x += v * f.x; a2.y += v * f.y;
    f = __half22float2(h[3]); a3.x += v * f.x; a3.y += v * f.y;
}

__device__ __forceinline__ void add8(float2& a0, float2& a1,
                                     float2& a2, float2& a3, uint4 u) {
    const __half2* h = reinterpret_cast<const __half2*>(&u);
    float2 f;
    f = __half22float2(h[0]); a0.x += f.x; a0.y += f.y;
    f = __half22float2(h[1]); a1.x += f.x; a1.y += f.y;
    f = __half22float2(h[2]); a2.x += f.x; a2.y += f.y;
    f = __half22float2(h[3]); a3.x += f.x; a3.y += f.y;
}

__device__ __forceinline__ uint4 pack8(float2 a0, float2 a1,
                                       float2 a2, float2 a3) {
    uint4 o;
    __half2* oh = reinterpret_cast<__half2*>(&o);
    oh[0] = __float22half2_rn(a0);
    oh[1] = __float22half2_rn(a1);
    oh[2] = __float22half2_rn(a2);
    oh[3] = __float22half2_rn(a3);
    return o;
}

template <bool FUSE_SUM>
__global__ void spmm_csr_kernel(int src_l, int dst_l) {
    int tid = blockIdx.x * blockDim.x + threadIdx.x;
    int row = tid >> 3;
    int c   = tid & 7;
    if (row >= N_TOTAL) return;

    const uint4* __restrict__ src = g_xh[src_l];
    uint4*       __restrict__ dst = g_xh[dst_l];

    int beg = __ldg(&g_off[row]);
    int end = __ldg(&g_off[row + 1]);

    float2 a0 = {0.f, 0.f}, a1 = {0.f, 0.f}, a2 = {0.f, 0.f}, a3 = {0.f, 0.f};
    int e = beg;
    for (; e + 3 < end; e += 4) {
        int2 p0 = __ldg(&g_edges[e]);
        int2 p1 = __ldg(&g_edges[e + 1]);
        int2 p2 = __ldg(&g_edges[e + 2]);
        int2 p3 = __ldg(&g_edges[e + 3]);
        uint4 u0 = __ldg(src + ((size_t)p0.x * 8 + c));
        uint4 u1 = __ldg(src + ((size_t)p1.x * 8 + c));
        uint4 u2 = __ldg(src + ((size_t)p2.x * 8 + c));
        uint4 u3 = __ldg(src + ((size_t)p3.x * 8 + c));
        acc8(a0, a1, a2, a3, u0, __int_as_float(p0.y));
        acc8(a0, a1, a2, a3, u1, __int_as_float(p1.y));
        acc8(a0, a1, a2, a3, u2, __int_as_float(p2.y));
        acc8(a0, a1, a2, a3, u3, __int_as_float(p3.y));
    }
    for (; e < end; e++) {
        int2 p = __ldg(&g_edges[e]);
        uint4 u = __ldg(src + ((size_t)p.x * 8 + c));
        acc8(a0, a1, a2, a3, u, __int_as_float(p.y));
    }

    size_t oidx = (size_t)row * 8 + c;
    __stcs(dst + oidx, pack8(a0, a1, a2, a3));

    if (FUSE_SUM) {
        // s = x0 + x1 + x2 ; src here is x1
        add8(a0, a1, a2, a3, __ldg(&g_xh[0][oidx]));
        add8(a0, a1, a2, a3, __ldg(src + oidx));
        __stcs(&g_xh[3][oidx], pack8(a0, a1, a2, a3));
    }
}

// ---------------------------------------------------------------------------
// final: per batch element, compute layer-3 rows u and i on the fly from x2,
// add s, dot, scale. 8 lanes per batch element; lane c owns dims [8c, 8c+8).
// ---------------------------------------------------------------------------
__global__ void final_kernel(const int* __restrict__ uid,
                             const int* __restrict__ iid,
                             float* __restrict__ out) {
    int tid = blockIdx.x * blockDim.x + threadIdx.x;
    if (tid >= BATCH * 8) return;
    int b = tid >> 3;
    int c = tid & 7;

    int ru = __ldg(uid + b);
    int ri = __ldg(iid + b) + NUM_USERS;

    const uint4* __restrict__ x2 = g_xh[2];

    float fu[8], fi[8];
    {   // s rows
        uint4 su = __ldg(&g_xh[3][(size_t)ru * 8 + c]);
        uint4 si = __ldg(&g_xh[3][(size_t)ri * 8 + c]);
        const __half2* hu = reinterpret_cast<const __half2*>(&su);
        const __half2* hi = reinterpret_cast<const __half2*>(&si);
        #pragma unroll
        for (int k = 0; k < 4; k++) {
            float2 f = __half22float2(hu[k]);
            fu[2 * k] = f.x; fu[2 * k + 1] = f.y;
            f = __half22float2(hi[k]);
            fi[2 * k] = f.x; fi[2 * k + 1] = f.y;
        }
    }

    // layer-3 row u
    {
        int beg = __ldg(&g_off[ru]);
        int end = __ldg(&g_off[ru + 1]);
        for (int e = beg; e < end; e++) {
            int2 p = __ldg(&g_edges[e]);
            uint4 u = __ldg(x2 + ((size_t)p.x * 8 + c));
            float v = __int_as_float(p.y);
            const __half2* h = reinterpret_cast<const __half2*>(&u);
            #pragma unroll
            for (int k = 0; k < 4; k++) {
                float2 f = __half22float2(h[k]);
                fu[2 * k]     += v * f.x;
                fu[2 * k + 1] += v * f.y;
            }
        }
    }
    // layer-3 row i
    {
        int beg = __ldg(&g_off[ri]);
        int end = __ldg(&g_off[ri + 1]);
        for (int e = beg; e < end; e++) {
            int2 p = __ldg(&g_edges[e]);
            uint4 u = __ldg(x2 + ((size_t)p.x * 8 + c));
            float v = __int_as_float(p.y);
            const __half2* h = reinterpret_cast<const __half2*>(&u);
            #pragma unroll
            for (int k = 0; k < 4; k++) {
                float2 f = __half22float2(h[k]);
                fi[2 * k]     += v * f.x;
                fi[2 * k + 1] += v * f.y;
            }
        }
    }

    float s = 0.f;
    #pragma unroll
    for (int k = 0; k < 8; k++) s += fu[k] * fi[k];

    #pragma unroll
    for (int o = 4; o > 0; o >>= 1)
        s += __shfl_down_sync(0xffffffffu, s, o, 8);

    if (c == 0) out[b] = s * (1.0f / 16.0f);
}

// ---------------------------------------------------------------------------
// kernel_launch
// inputs: user_ids, item_ids, adj_row, adj_col, adj_val, user_emb_w, item_emb_w
// ---------------------------------------------------------------------------
extern "C" void kernel_launch(void* const* d_in, const int* in_sizes, int n_in,
                              void* d_out, int out_size) {
    const int*   uid  = (const int*)  d_in[0];
    const int*   iid  = (const int*)  d_in[1];
    const int*   rows = (const int*)  d_in[2];
    const int*   cols = (const int*)  d_in[3];
    const float* vals = (const float*)d_in[4];
    const float4* uw  = (const float4*)d_in[5];
    const float4* iw  = (const float4*)d_in[6];
    float* out = (float*)d_out;

    const int TB = 256;
    const int edge_blocks  = (NNZ + TB - 1) / TB;
    const int si_threads   = (NNZ > N_TOTAL * 8) ? NNZ : N_TOTAL * 8;
    const int si_blocks    = (si_threads + TB - 1) / TB;
    const int spmm_blocks  = (N_TOTAL * 8 + TB - 1) / TB;
    const int final_blocks = (BATCH * 8 + TB - 1) / TB;

    hist_kernel<<<edge_blocks, TB>>>(rows);
    scan_local_kernel<<<NB_SCAN, SCAN_B>>>();
    scan_add2_kernel<<<NB_SCAN, SCAN_B>>>();
    scatter_init_kernel<<<si_blocks, TB>>>(rows, cols, vals, uw, iw);

    spmm_csr_kernel<false><<<spmm_blocks, TB>>>(0, 1);   // x1 = A x0
    spmm_csr_kernel<true ><<<spmm_blocks, TB>>>(1, 2);   // x2 = A x1, s = x0+x1+x2

    final_kernel<<<final_blocks, TB>>>(uid, iid, out);
}